// round 3
// baseline (speedup 1.0000x reference)
#include <cuda_runtime.h>
#include <math.h>

// Problem constants (fixed shapes from reference)
constexpr int Bsz  = 4;
constexpr int Fdim = 2048;
constexpr int Tdim = 2048;
constexpr int Hdim = 1024;   // hidden
constexpr int NH   = 16;     // heads
constexpr int HS   = 64;     // head size
constexpr int Mrows = Bsz * Fdim;  // 8192

// Scratch for projected Q/K/V, stored head-major: [B, NH, S, HS]
__device__ float g_Q[(size_t)Bsz * NH * Fdim * HS];
__device__ float g_K[(size_t)Bsz * NH * Tdim * HS];
__device__ float g_V[(size_t)Bsz * NH * Tdim * HS];

// ---------------------------------------------------------------------------
// Fused projection GEMM: C[m, j] = sum_h X[m,h] * W[h,j] + bias[j]
//   X: [B*S, 1024], W: [1024, 1024] (H outer, j = n*64+d inner), bias: [1024]
//   Output written permuted to [B, NH, S, HS].
//   blockIdx.z selects (Q | K | V).
// Tile: 128x128x16, 256 threads, 8x8 per-thread microtile.  smem = 16 KB.
// ---------------------------------------------------------------------------
__global__ __launch_bounds__(256) void proj_kernel(
    const float* __restrict__ Xq,
    const float* __restrict__ Xkv,
    const float* __restrict__ Wq, const float* __restrict__ bq,
    const float* __restrict__ Wk, const float* __restrict__ bk,
    const float* __restrict__ Wv, const float* __restrict__ bv)
{
    __shared__ float As[16][128];  // [k][m] (transposed on load)
    __shared__ float Bs[16][128];  // [k][j]

    const float* X;  const float* W;  const float* bias;  float* out;
    if (blockIdx.z == 0)      { X = Xq;  W = Wq; bias = bq; out = g_Q; }
    else if (blockIdx.z == 1) { X = Xkv; W = Wk; bias = bk; out = g_K; }
    else                      { X = Xkv; W = Wv; bias = bv; out = g_V; }

    const int tid = threadIdx.x;
    const int m0 = blockIdx.y * 128;
    const int n0 = blockIdx.x * 128;

    const int rowbase = (tid / 16) * 8;
    const int colbase = (tid % 16) * 8;

    const int a_row = tid / 4;
    const int a_k4  = (tid % 4) * 4;
    const int b_k   = tid / 32;
    const int b_c4  = (tid % 32) * 4;

    float acc[8][8];
#pragma unroll
    for (int i = 0; i < 8; i++)
#pragma unroll
        for (int j = 0; j < 8; j++) acc[i][j] = 0.f;

    for (int k0 = 0; k0 < Hdim; k0 += 16) {
        __syncthreads();
        // Load A tile (128 rows x 16 k), transpose into As[k][m]
#pragma unroll
        for (int i = 0; i < 2; i++) {
            int r = a_row + i * 64;
            float4 v = *(const float4*)&X[(size_t)(m0 + r) * Hdim + k0 + a_k4];
            As[a_k4 + 0][r] = v.x;
            As[a_k4 + 1][r] = v.y;
            As[a_k4 + 2][r] = v.z;
            As[a_k4 + 3][r] = v.w;
        }
        // Load B tile (16 k x 128 cols) direct
#pragma unroll
        for (int i = 0; i < 2; i++) {
            int kk = b_k + i * 8;
            *(float4*)&Bs[kk][b_c4] =
                *(const float4*)&W[(size_t)(k0 + kk) * 1024 + n0 + b_c4];
        }
        __syncthreads();

#pragma unroll
        for (int kk = 0; kk < 16; kk++) {
            float a[8], bb[8];
            *(float4*)&a[0]  = *(float4*)&As[kk][rowbase];
            *(float4*)&a[4]  = *(float4*)&As[kk][rowbase + 4];
            *(float4*)&bb[0] = *(float4*)&Bs[kk][colbase];
            *(float4*)&bb[4] = *(float4*)&Bs[kk][colbase + 4];
#pragma unroll
            for (int i = 0; i < 8; i++)
#pragma unroll
                for (int j = 0; j < 8; j++)
                    acc[i][j] += a[i] * bb[j];
        }
    }

    // Epilogue: add bias, store permuted [B, NH, S, HS]
    float bj[8];
    *(float4*)&bj[0] = *(const float4*)&bias[n0 + colbase];
    *(float4*)&bj[4] = *(const float4*)&bias[n0 + colbase + 4];

    const int S = 2048;               // F == T == 2048
    const int j0 = n0 + colbase;
    const int n_head = j0 / HS;       // 8-wide column group never crosses a head
    const int d0 = j0 % HS;

#pragma unroll
    for (int i = 0; i < 8; i++) {
        int m = m0 + rowbase + i;
        int b_idx = m / S;
        int s_idx = m % S;
        float* orow = &out[(((size_t)b_idx * NH + n_head) * S + s_idx) * HS + d0];
        float4 v0, v1;
        v0.x = acc[i][0] + bj[0]; v0.y = acc[i][1] + bj[1];
        v0.z = acc[i][2] + bj[2]; v0.w = acc[i][3] + bj[3];
        v1.x = acc[i][4] + bj[4]; v1.y = acc[i][5] + bj[5];
        v1.z = acc[i][6] + bj[6]; v1.w = acc[i][7] + bj[7];
        *(float4*)&orow[0] = v0;
        *(float4*)&orow[4] = v1;
    }
}

// ---------------------------------------------------------------------------
// Fused flash-style attention (fp32, online softmax).
// Grid: (F/64, NH, B). Block: 256 threads (16x16), 4x4 microtiles.
// Per iteration over T in 64-wide tiles:
//   S = (Q K^T) * 1/8 + (1-mask)*(-1e4);  online softmax;  O += P V
// smem = 48 KB total: Qs 16K + KPs 16K (K^T tile, then reused for P) + Vs 16K.
// Output: [B, F, NH, HS]
// ---------------------------------------------------------------------------
__global__ __launch_bounds__(256) void attn_kernel(
    const float* __restrict__ mask,   // [B, F, T]
    float* __restrict__ out)          // [B, F, NH, HS]
{
    __shared__ float Qs[64][64];    // [d][r]
    __shared__ float KPs[64][64];   // phase 1: K^T [d][t]; phase 2: P [r][t]
    __shared__ float Vs[64][64];    // [t][d]

    const int tid = threadIdx.x;
    const int tx = tid % 16;
    const int ty = tid / 16;
    const int f0 = blockIdx.x * 64;
    const int n  = blockIdx.y;
    const int b  = blockIdx.z;

    const float* Qb = g_Q + (((size_t)b * NH + n) * Fdim + f0) * HS;
    const float* Kb = g_K + (((size_t)b * NH + n) * Tdim) * HS;
    const float* Vb = g_V + (((size_t)b * NH + n) * Tdim) * HS;
    const float* Mb = mask + ((size_t)b * Fdim + f0) * Tdim;

    // Load Q tile transposed: Qs[d][r]
    {
        int r = tid / 4;
        int q = tid % 4;
#pragma unroll
        for (int i = 0; i < 4; i++) {
            int d0 = (q + i * 4) * 4;
            float4 v = *(const float4*)&Qb[(size_t)r * HS + d0];
            Qs[d0 + 0][r] = v.x;
            Qs[d0 + 1][r] = v.y;
            Qs[d0 + 2][r] = v.z;
            Qs[d0 + 3][r] = v.w;
        }
    }

    float m_i[4], l_i[4], o[4][4];
#pragma unroll
    for (int i = 0; i < 4; i++) {
        m_i[i] = -1e30f;
        l_i[i] = 0.f;
#pragma unroll
        for (int j = 0; j < 4; j++) o[i][j] = 0.f;
    }

    const float inv_sqrt = 0.125f;  // 1/sqrt(64)

    for (int t0 = 0; t0 < Tdim; t0 += 64) {
        __syncthreads();  // prior iteration's P/V reads (and Qs writes, iter 0) done
        // Load K transposed into KPs + V direct
        {
            int r = tid / 4;
            int q = tid % 4;
#pragma unroll
            for (int i = 0; i < 4; i++) {
                int d0 = (q + i * 4) * 4;
                float4 v = *(const float4*)&Kb[(size_t)(t0 + r) * HS + d0];
                KPs[d0 + 0][r] = v.x;
                KPs[d0 + 1][r] = v.y;
                KPs[d0 + 2][r] = v.z;
                KPs[d0 + 3][r] = v.w;
                *(float4*)&Vs[r][d0] =
                    *(const float4*)&Vb[(size_t)(t0 + r) * HS + d0];
            }
        }
        __syncthreads();

        // S = Q K^T  (4x4 per thread)
        float s[4][4];
#pragma unroll
        for (int i = 0; i < 4; i++)
#pragma unroll
            for (int j = 0; j < 4; j++) s[i][j] = 0.f;

#pragma unroll
        for (int d = 0; d < 64; d++) {
            float a[4], bb[4];
            *(float4*)a  = *(float4*)&Qs[d][ty * 4];
            *(float4*)bb = *(float4*)&KPs[d][tx * 4];
#pragma unroll
            for (int i = 0; i < 4; i++)
#pragma unroll
                for (int j = 0; j < 4; j++)
                    s[i][j] += a[i] * bb[j];
        }

        // scale + mask adder
#pragma unroll
        for (int i = 0; i < 4; i++) {
            float4 mv = *(const float4*)&Mb[(size_t)(ty * 4 + i) * Tdim + t0 + tx * 4];
            s[i][0] = s[i][0] * inv_sqrt + (1.f - mv.x) * (-10000.f);
            s[i][1] = s[i][1] * inv_sqrt + (1.f - mv.y) * (-10000.f);
            s[i][2] = s[i][2] * inv_sqrt + (1.f - mv.z) * (-10000.f);
            s[i][3] = s[i][3] * inv_sqrt + (1.f - mv.w) * (-10000.f);
        }

        // online softmax
        float p[4][4];
#pragma unroll
        for (int i = 0; i < 4; i++) {
            float mx = fmaxf(fmaxf(s[i][0], s[i][1]), fmaxf(s[i][2], s[i][3]));
            mx = fmaxf(mx, __shfl_xor_sync(0xffffffffu, mx, 1));
            mx = fmaxf(mx, __shfl_xor_sync(0xffffffffu, mx, 2));
            mx = fmaxf(mx, __shfl_xor_sync(0xffffffffu, mx, 4));
            mx = fmaxf(mx, __shfl_xor_sync(0xffffffffu, mx, 8));

            float mnew = fmaxf(m_i[i], mx);
            float scale = __expf(m_i[i] - mnew);
            m_i[i] = mnew;

            float rs = 0.f;
#pragma unroll
            for (int j = 0; j < 4; j++) {
                p[i][j] = __expf(s[i][j] - mnew);
                rs += p[i][j];
            }
            rs += __shfl_xor_sync(0xffffffffu, rs, 1);
            rs += __shfl_xor_sync(0xffffffffu, rs, 2);
            rs += __shfl_xor_sync(0xffffffffu, rs, 4);
            rs += __shfl_xor_sync(0xffffffffu, rs, 8);

            l_i[i] = l_i[i] * scale + rs;
#pragma unroll
            for (int j = 0; j < 4; j++) o[i][j] *= scale;
        }

        __syncthreads();  // all threads done reading KPs as K^T

        // write P (row-major) into KPs
#pragma unroll
        for (int i = 0; i < 4; i++) {
            float4 pv;
            pv.x = p[i][0]; pv.y = p[i][1]; pv.z = p[i][2]; pv.w = p[i][3];
            *(float4*)&KPs[ty * 4 + i][tx * 4] = pv;
        }
        __syncthreads();

        // O += P V
#pragma unroll
        for (int t = 0; t < 64; t++) {
            float bb[4];
            *(float4*)bb = *(float4*)&Vs[t][tx * 4];
            float a0 = KPs[ty * 4 + 0][t];
            float a1 = KPs[ty * 4 + 1][t];
            float a2 = KPs[ty * 4 + 2][t];
            float a3 = KPs[ty * 4 + 3][t];
#pragma unroll
            for (int j = 0; j < 4; j++) {
                o[0][j] += a0 * bb[j];
                o[1][j] += a1 * bb[j];
                o[2][j] += a2 * bb[j];
                o[3][j] += a3 * bb[j];
            }
        }
    }

    // epilogue: normalize and store [B, F, NH, HS]
#pragma unroll
    for (int i = 0; i < 4; i++) {
        float invl = 1.f / l_i[i];
        float4 v;
        v.x = o[i][0] * invl;
        v.y = o[i][1] * invl;
        v.z = o[i][2] * invl;
        v.w = o[i][3] * invl;
        int f = f0 + ty * 4 + i;
        float* orow = &out[(((size_t)b * Fdim + f) * NH + n) * HS + tx * 4];
        *(float4*)orow = v;
    }
}

// ---------------------------------------------------------------------------
extern "C" void kernel_launch(void* const* d_in, const int* in_sizes, int n_in,
                              void* d_out, int out_size)
{
    const float* from = (const float*)d_in[0];  // [B,F,H]
    const float* to   = (const float*)d_in[1];  // [B,T,H]
    const float* mask = (const float*)d_in[2];  // [B,F,T]
    const float* Wq   = (const float*)d_in[3];
    const float* bq   = (const float*)d_in[4];
    const float* Wk   = (const float*)d_in[5];
    const float* bk   = (const float*)d_in[6];
    const float* Wv   = (const float*)d_in[7];
    const float* bv   = (const float*)d_in[8];
    float* out = (float*)d_out;

    // 1) Q/K/V projections (fused into one launch via grid.z)
    dim3 pgrid(1024 / 128, Mrows / 128, 3);
    proj_kernel<<<pgrid, 256>>>(from, to, Wq, bq, Wk, bk, Wv, bv);

    // 2) fused masked-softmax attention
    dim3 agrid(Fdim / 64, NH, Bsz);
    attn_kernel<<<agrid, 256>>>(mask, out);
}

// round 4
// speedup vs baseline: 1.9792x; 1.9792x over previous
#include <cuda_runtime.h>
#include <cuda_bf16.h>
#include <math.h>
#include <stdint.h>

constexpr int Bsz  = 4;
constexpr int Fdim = 2048;
constexpr int Tdim = 2048;
constexpr int Hdim = 1024;
constexpr int NH   = 16;
constexpr int HS   = 64;

// Projected Q/K/V scratch, head-major: [B, NH, S, HS] fp32
__device__ float g_Q[(size_t)Bsz * NH * Fdim * HS];
__device__ float g_K[(size_t)Bsz * NH * Tdim * HS];
__device__ float g_V[(size_t)Bsz * NH * Tdim * HS];

// ---------------------------------------------------------------------------
// helpers
// ---------------------------------------------------------------------------
__device__ __forceinline__ uint32_t smem_u32(const void* p) {
    return (uint32_t)__cvta_generic_to_shared(p);
}
__device__ __forceinline__ void ldsm_x4(uint32_t& r0, uint32_t& r1,
                                        uint32_t& r2, uint32_t& r3, uint32_t a) {
    asm volatile("ldmatrix.sync.aligned.m8n8.x4.shared.b16 {%0,%1,%2,%3}, [%4];"
                 : "=r"(r0), "=r"(r1), "=r"(r2), "=r"(r3) : "r"(a));
}
__device__ __forceinline__ void ldsm_x2(uint32_t& r0, uint32_t& r1, uint32_t a) {
    asm volatile("ldmatrix.sync.aligned.m8n8.x2.shared.b16 {%0,%1}, [%2];"
                 : "=r"(r0), "=r"(r1) : "r"(a));
}
__device__ __forceinline__ void ldsm_x2t(uint32_t& r0, uint32_t& r1, uint32_t a) {
    asm volatile("ldmatrix.sync.aligned.m8n8.x2.trans.shared.b16 {%0,%1}, [%2];"
                 : "=r"(r0), "=r"(r1) : "r"(a));
}
__device__ __forceinline__ void mma16816(float* c, const uint32_t* a, const uint32_t* b) {
    asm volatile(
        "mma.sync.aligned.m16n8k16.row.col.f32.bf16.bf16.f32 "
        "{%0,%1,%2,%3}, {%4,%5,%6,%7}, {%8,%9}, {%0,%1,%2,%3};"
        : "+f"(c[0]), "+f"(c[1]), "+f"(c[2]), "+f"(c[3])
        : "r"(a[0]), "r"(a[1]), "r"(a[2]), "r"(a[3]), "r"(b[0]), "r"(b[1]));
}
__device__ __forceinline__ uint32_t pack_bf2(float lo_elem, float hi_elem) {
    __nv_bfloat162 t = __floats2bfloat162_rn(lo_elem, hi_elem);
    return *reinterpret_cast<uint32_t*>(&t);
}
// split (x,y) into hi-pair and lo-pair packed b32
__device__ __forceinline__ void split_pack2(float x, float y, uint32_t& hi, uint32_t& lo) {
    __nv_bfloat16 hx = __float2bfloat16_rn(x);
    __nv_bfloat16 hy = __float2bfloat16_rn(y);
    __nv_bfloat162 hp = __halves2bfloat162(hx, hy);
    hi = *reinterpret_cast<uint32_t*>(&hp);
    lo = pack_bf2(x - __bfloat162float(hx), y - __bfloat162float(hy));
}
// split a float4 into 4 hi bf16 + 4 lo bf16, stored to smem
__device__ __forceinline__ void split_store4(__nv_bfloat16* h, __nv_bfloat16* l, float4 v) {
    __nv_bfloat16 hx = __float2bfloat16_rn(v.x);
    __nv_bfloat16 hy = __float2bfloat16_rn(v.y);
    __nv_bfloat16 hz = __float2bfloat16_rn(v.z);
    __nv_bfloat16 hw = __float2bfloat16_rn(v.w);
    *(__nv_bfloat162*)(h + 0) = __halves2bfloat162(hx, hy);
    *(__nv_bfloat162*)(h + 2) = __halves2bfloat162(hz, hw);
    *(__nv_bfloat162*)(l + 0) = __floats2bfloat162_rn(v.x - __bfloat162float(hx),
                                                      v.y - __bfloat162float(hy));
    *(__nv_bfloat162*)(l + 2) = __floats2bfloat162_rn(v.z - __bfloat162float(hz),
                                                      v.w - __bfloat162float(hw));
}

// ---------------------------------------------------------------------------
// Projection GEMM (bf16 split, tensor cores).
// C[m,j] = sum_h X[m,h] W[h,j] + bias[j], written permuted to [B,NH,S,HS].
// Block: 128(M) x 64(N), 4 warps (warp tile 64x32), K-step 32.
// blockIdx.z selects Q/K/V.
// ---------------------------------------------------------------------------
__global__ __launch_bounds__(128, 3) void proj_kernel(
    const float* __restrict__ Xq,
    const float* __restrict__ Xkv,
    const float* __restrict__ Wq, const float* __restrict__ bq,
    const float* __restrict__ Wk, const float* __restrict__ bk,
    const float* __restrict__ Wv, const float* __restrict__ bv)
{
    __shared__ __nv_bfloat16 AsH[128][40], AsL[128][40];   // [m][k]
    __shared__ __nv_bfloat16 BsH[32][72],  BsL[32][72];    // [k][n]

    const float* X;  const float* W;  const float* bias;  float* out;
    if (blockIdx.z == 0)      { X = Xq;  W = Wq; bias = bq; out = g_Q; }
    else if (blockIdx.z == 1) { X = Xkv; W = Wk; bias = bk; out = g_K; }
    else                      { X = Xkv; W = Wv; bias = bv; out = g_V; }

    const int tid  = threadIdx.x;
    const int warp = tid >> 5;
    const int lane = tid & 31;
    const int g    = lane >> 2;
    const int tg   = lane & 3;

    const int m0 = blockIdx.y * 128;
    const int n0 = blockIdx.x * 64;
    const int wm = (warp >> 1) * 64;   // warp M offset
    const int wn = (warp & 1) * 32;    // warp N offset

    float acc[4][4][4] = {};           // [mi][ni][4]

    const int a_row = tid;             // 0..127
    const int b_row = tid >> 2;        // 0..31
    const int b_seg = tid & 3;

    for (int k0 = 0; k0 < Hdim; k0 += 32) {
        __syncthreads();
        // A tile: 128 x 32 fp32 -> split bf16
#pragma unroll
        for (int i = 0; i < 8; i++) {
            float4 v = *(const float4*)&X[(size_t)(m0 + a_row) * Hdim + k0 + i * 4];
            split_store4(&AsH[a_row][i * 4], &AsL[a_row][i * 4], v);
        }
        // B tile: 32 x 64 fp32 -> split bf16
#pragma unroll
        for (int i = 0; i < 4; i++) {
            float4 v = *(const float4*)&W[(size_t)(k0 + b_row) * 1024 + n0 + b_seg * 16 + i * 4];
            split_store4(&BsH[b_row][b_seg * 16 + i * 4], &BsL[b_row][b_seg * 16 + i * 4], v);
        }
        __syncthreads();

#pragma unroll
        for (int kk = 0; kk < 32; kk += 16) {
            uint32_t aH[4][4], aL[4][4];
            const int ar = (lane & 15);
            const int ac = kk + (lane >> 4) * 8;
#pragma unroll
            for (int mi = 0; mi < 4; mi++) {
                ldsm_x4(aH[mi][0], aH[mi][1], aH[mi][2], aH[mi][3],
                        smem_u32(&AsH[wm + mi * 16 + ar][ac]));
                ldsm_x4(aL[mi][0], aL[mi][1], aL[mi][2], aL[mi][3],
                        smem_u32(&AsL[wm + mi * 16 + ar][ac]));
            }
            uint32_t bH[4][2], bL[4][2];
            const int br = kk + (lane & 15);
#pragma unroll
            for (int ni = 0; ni < 4; ni++) {
                ldsm_x2t(bH[ni][0], bH[ni][1], smem_u32(&BsH[br][wn + ni * 8]));
                ldsm_x2t(bL[ni][0], bL[ni][1], smem_u32(&BsL[br][wn + ni * 8]));
            }
#pragma unroll
            for (int mi = 0; mi < 4; mi++)
#pragma unroll
                for (int ni = 0; ni < 4; ni++) {
                    mma16816(acc[mi][ni], aH[mi], bH[ni]);
                    mma16816(acc[mi][ni], aH[mi], bL[ni]);
                    mma16816(acc[mi][ni], aL[mi], bH[ni]);
                }
        }
    }

    // epilogue: bias + permuted store [B, NH, S, HS]
#pragma unroll
    for (int ni = 0; ni < 4; ni++) {
        const int col = n0 + wn + ni * 8 + tg * 2;
        const int head = col >> 6;
        const int d = col & 63;
        float2 bv2 = *(const float2*)&bias[col];
#pragma unroll
        for (int mi = 0; mi < 4; mi++) {
            int m  = m0 + wm + mi * 16 + g;
            int bi = m >> 11, si = m & 2047;
            float2 r0 = { acc[mi][ni][0] + bv2.x, acc[mi][ni][1] + bv2.y };
            *(float2*)&out[(((size_t)bi * NH + head) * 2048 + si) * HS + d] = r0;
            m  = m + 8;
            bi = m >> 11; si = m & 2047;
            float2 r1 = { acc[mi][ni][2] + bv2.x, acc[mi][ni][3] + bv2.y };
            *(float2*)&out[(((size_t)bi * NH + head) * 2048 + si) * HS + d] = r1;
        }
    }
}

// ---------------------------------------------------------------------------
// Flash attention (bf16 split tensor cores, online softmax).
// Block: 128 F-rows x 64 T-tile, 8 warps (one m16 row-band each).
// Q fragments loaded direct from gmem (scale 1/8 folded into split).
// ---------------------------------------------------------------------------
__global__ __launch_bounds__(256, 2) void attn_kernel(
    const float* __restrict__ mask,   // [B, F, T]
    float* __restrict__ out)          // [B, F, NH, HS]
{
    __shared__ __nv_bfloat16 KsH[64][72], KsL[64][72];   // [t][hs]
    __shared__ __nv_bfloat16 VsH[64][72], VsL[64][72];   // [t][d]

    const int tid  = threadIdx.x;
    const int warp = tid >> 5;
    const int lane = tid & 31;
    const int g    = lane >> 2;
    const int tg   = lane & 3;

    const int f0 = blockIdx.x * 128;
    const int n  = blockIdx.y;
    const int b  = blockIdx.z;

    const float* Qw = g_Q + (((size_t)b * NH + n) * Fdim + f0 + warp * 16) * HS;
    const float* Kb = g_K + (((size_t)b * NH + n) * Tdim) * HS;
    const float* Vb = g_V + (((size_t)b * NH + n) * Tdim) * HS;
    const float* Mw = mask + ((size_t)b * Fdim + f0 + warp * 16) * Tdim;

    // Q fragments: 4 k16 chunks, hi/lo, scaled by 1/8 (exact power of 2)
    uint32_t qH[4][4], qL[4][4];
#pragma unroll
    for (int kc = 0; kc < 4; kc++) {
        float2 v0 = *(const float2*)&Qw[(size_t)g * HS + kc * 16 + tg * 2];
        float2 v1 = *(const float2*)&Qw[(size_t)(g + 8) * HS + kc * 16 + tg * 2];
        float2 v2 = *(const float2*)&Qw[(size_t)g * HS + kc * 16 + 8 + tg * 2];
        float2 v3 = *(const float2*)&Qw[(size_t)(g + 8) * HS + kc * 16 + 8 + tg * 2];
        split_pack2(v0.x * 0.125f, v0.y * 0.125f, qH[kc][0], qL[kc][0]);
        split_pack2(v1.x * 0.125f, v1.y * 0.125f, qH[kc][1], qL[kc][1]);
        split_pack2(v2.x * 0.125f, v2.y * 0.125f, qH[kc][2], qL[kc][2]);
        split_pack2(v3.x * 0.125f, v3.y * 0.125f, qH[kc][3], qL[kc][3]);
    }

    float o[8][4] = {};
    float mrow0 = -1e30f, mrow1 = -1e30f, l0 = 0.f, l1 = 0.f;

    const int ld_row = tid >> 2;     // 0..63
    const int ld_seg = tid & 3;

    for (int t0 = 0; t0 < Tdim; t0 += 64) {
        __syncthreads();
        // load + split K and V tiles (64 x 64 fp32 each)
#pragma unroll
        for (int i = 0; i < 4; i++) {
            int col = ld_seg * 16 + i * 4;
            float4 kv = *(const float4*)&Kb[(size_t)(t0 + ld_row) * HS + col];
            split_store4(&KsH[ld_row][col], &KsL[ld_row][col], kv);
            float4 vv = *(const float4*)&Vb[(size_t)(t0 + ld_row) * HS + col];
            split_store4(&VsH[ld_row][col], &VsL[ld_row][col], vv);
        }
        __syncthreads();

        // S = Q K^T (scaled) : 8 n8-tiles over T
        float s[8][4];
#pragma unroll
        for (int ni = 0; ni < 8; ni++) {
            s[ni][0] = s[ni][1] = s[ni][2] = s[ni][3] = 0.f;
            const int kr = ni * 8 + (lane & 7);
#pragma unroll
            for (int kc = 0; kc < 4; kc++) {
                const int kcol = kc * 16 + ((lane & 15) >> 3) * 8;
                uint32_t kH[2], kL[2];
                ldsm_x2(kH[0], kH[1], smem_u32(&KsH[kr][kcol]));
                ldsm_x2(kL[0], kL[1], smem_u32(&KsL[kr][kcol]));
                mma16816(s[ni], qH[kc], kH);
                mma16816(s[ni], qH[kc], kL);
                mma16816(s[ni], qL[kc], kH);
            }
            // mask adder
            float2 mm0 = *(const float2*)&Mw[(size_t)g * Tdim + t0 + ni * 8 + tg * 2];
            float2 mm1 = *(const float2*)&Mw[(size_t)(g + 8) * Tdim + t0 + ni * 8 + tg * 2];
            s[ni][0] += (1.f - mm0.x) * (-10000.f);
            s[ni][1] += (1.f - mm0.y) * (-10000.f);
            s[ni][2] += (1.f - mm1.x) * (-10000.f);
            s[ni][3] += (1.f - mm1.y) * (-10000.f);
        }

        // online softmax (rows g and g+8; row spread over 4 lanes)
        float rmax0 = -1e30f, rmax1 = -1e30f;
#pragma unroll
        for (int ni = 0; ni < 8; ni++) {
            rmax0 = fmaxf(rmax0, fmaxf(s[ni][0], s[ni][1]));
            rmax1 = fmaxf(rmax1, fmaxf(s[ni][2], s[ni][3]));
        }
        rmax0 = fmaxf(rmax0, __shfl_xor_sync(0xffffffffu, rmax0, 1));
        rmax0 = fmaxf(rmax0, __shfl_xor_sync(0xffffffffu, rmax0, 2));
        rmax1 = fmaxf(rmax1, __shfl_xor_sync(0xffffffffu, rmax1, 1));
        rmax1 = fmaxf(rmax1, __shfl_xor_sync(0xffffffffu, rmax1, 2));

        float mnew0 = fmaxf(mrow0, rmax0);
        float mnew1 = fmaxf(mrow1, rmax1);
        float esc0 = __expf(mrow0 - mnew0);
        float esc1 = __expf(mrow1 - mnew1);
        mrow0 = mnew0;  mrow1 = mnew1;

        float rs0 = 0.f, rs1 = 0.f;
#pragma unroll
        for (int ni = 0; ni < 8; ni++) {
            s[ni][0] = __expf(s[ni][0] - mnew0);
            s[ni][1] = __expf(s[ni][1] - mnew0);
            s[ni][2] = __expf(s[ni][2] - mnew1);
            s[ni][3] = __expf(s[ni][3] - mnew1);
            rs0 += s[ni][0] + s[ni][1];
            rs1 += s[ni][2] + s[ni][3];
        }
        rs0 += __shfl_xor_sync(0xffffffffu, rs0, 1);
        rs0 += __shfl_xor_sync(0xffffffffu, rs0, 2);
        rs1 += __shfl_xor_sync(0xffffffffu, rs1, 1);
        rs1 += __shfl_xor_sync(0xffffffffu, rs1, 2);

        l0 = l0 * esc0 + rs0;
        l1 = l1 * esc1 + rs1;
#pragma unroll
        for (int di = 0; di < 8; di++) {
            o[di][0] *= esc0;  o[di][1] *= esc0;
            o[di][2] *= esc1;  o[di][3] *= esc1;
        }

        // O += P V  (P built register-only from S fragments)
#pragma unroll
        for (int kc = 0; kc < 4; kc++) {
            uint32_t pH[4], pL[4];
            split_pack2(s[2 * kc][0],     s[2 * kc][1],     pH[0], pL[0]);
            split_pack2(s[2 * kc][2],     s[2 * kc][3],     pH[1], pL[1]);
            split_pack2(s[2 * kc + 1][0], s[2 * kc + 1][1], pH[2], pL[2]);
            split_pack2(s[2 * kc + 1][2], s[2 * kc + 1][3], pH[3], pL[3]);
            const int vr = kc * 16 + (lane & 15);
#pragma unroll
            for (int di = 0; di < 8; di++) {
                uint32_t vH[2], vL[2];
                ldsm_x2t(vH[0], vH[1], smem_u32(&VsH[vr][di * 8]));
                ldsm_x2t(vL[0], vL[1], smem_u32(&VsL[vr][di * 8]));
                mma16816(o[di], pH, vH);
                mma16816(o[di], pH, vL);
                mma16816(o[di], pL, vH);
            }
        }
    }

    // epilogue: normalize, store [B, F, NH, HS]
    const float inv0 = 1.f / l0;
    const float inv1 = 1.f / l1;
    const int f = f0 + warp * 16 + g;
    float* orow0 = out + (((size_t)b * Fdim + f) * NH + n) * HS;
    float* orow1 = out + (((size_t)b * Fdim + f + 8) * NH + n) * HS;
#pragma unroll
    for (int di = 0; di < 8; di++) {
        float2 r0 = { o[di][0] * inv0, o[di][1] * inv0 };
        float2 r1 = { o[di][2] * inv1, o[di][3] * inv1 };
        *(float2*)&orow0[di * 8 + tg * 2] = r0;
        *(float2*)&orow1[di * 8 + tg * 2] = r1;
    }
}

// ---------------------------------------------------------------------------
extern "C" void kernel_launch(void* const* d_in, const int* in_sizes, int n_in,
                              void* d_out, int out_size)
{
    const float* from = (const float*)d_in[0];
    const float* to   = (const float*)d_in[1];
    const float* mask = (const float*)d_in[2];
    const float* Wq   = (const float*)d_in[3];
    const float* bq   = (const float*)d_in[4];
    const float* Wk   = (const float*)d_in[5];
    const float* bk   = (const float*)d_in[6];
    const float* Wv   = (const float*)d_in[7];
    const float* bv   = (const float*)d_in[8];
    float* out = (float*)d_out;

    dim3 pgrid(Hdim / 64, (Bsz * Fdim) / 128, 3);
    proj_kernel<<<pgrid, 128>>>(from, to, Wq, bq, Wk, bk, Wv, bv);

    dim3 agrid(Fdim / 128, NH, Bsz);
    attn_kernel<<<agrid, 256>>>(mask, out);
}

// round 5
// speedup vs baseline: 2.4797x; 1.2528x over previous
#include <cuda_runtime.h>
#include <cuda_bf16.h>
#include <math.h>
#include <stdint.h>

constexpr int Bsz  = 4;
constexpr int Fdim = 2048;
constexpr int Tdim = 2048;
constexpr int Hdim = 1024;
constexpr int NH   = 16;
constexpr int HS   = 64;

// ---------------------------------------------------------------------------
// bf16 split scratch (hi + lo), all in gmem
// ---------------------------------------------------------------------------
// X: rows 0..8191 = from_tensor, rows 8192..16383 = to_tensor   [16384 x 1024]
__device__ __nv_bfloat16 g_Xh[(size_t)16384 * 1024];
__device__ __nv_bfloat16 g_Xl[(size_t)16384 * 1024];
// W: z-th slice is Wq / Wk / Wv   [3 x 1024 x 1024]
__device__ __nv_bfloat16 g_Wh[(size_t)3 * 1024 * 1024];
__device__ __nv_bfloat16 g_Wl[(size_t)3 * 1024 * 1024];
// projected Q/K/V  [B, NH, S, HS]  (Q pre-scaled by 1/8)
__device__ __nv_bfloat16 g_Qh[(size_t)Bsz * NH * Fdim * HS];
__device__ __nv_bfloat16 g_Ql[(size_t)Bsz * NH * Fdim * HS];
__device__ __nv_bfloat16 g_Kh[(size_t)Bsz * NH * Tdim * HS];
__device__ __nv_bfloat16 g_Kl[(size_t)Bsz * NH * Tdim * HS];
__device__ __nv_bfloat16 g_Vh[(size_t)Bsz * NH * Tdim * HS];
__device__ __nv_bfloat16 g_Vl[(size_t)Bsz * NH * Tdim * HS];

// ---------------------------------------------------------------------------
// helpers
// ---------------------------------------------------------------------------
__device__ __forceinline__ uint32_t smem_u32(const void* p) {
    return (uint32_t)__cvta_generic_to_shared(p);
}
__device__ __forceinline__ void ldsm_x4(uint32_t* r, uint32_t a) {
    asm volatile("ldmatrix.sync.aligned.m8n8.x4.shared.b16 {%0,%1,%2,%3}, [%4];"
                 : "=r"(r[0]), "=r"(r[1]), "=r"(r[2]), "=r"(r[3]) : "r"(a));
}
__device__ __forceinline__ void ldsm_x4t(uint32_t* r, uint32_t a) {
    asm volatile("ldmatrix.sync.aligned.m8n8.x4.trans.shared.b16 {%0,%1,%2,%3}, [%4];"
                 : "=r"(r[0]), "=r"(r[1]), "=r"(r[2]), "=r"(r[3]) : "r"(a));
}
__device__ __forceinline__ void mma16816(float* c, const uint32_t* a, const uint32_t* b) {
    asm volatile(
        "mma.sync.aligned.m16n8k16.row.col.f32.bf16.bf16.f32 "
        "{%0,%1,%2,%3}, {%4,%5,%6,%7}, {%8,%9}, {%0,%1,%2,%3};"
        : "+f"(c[0]), "+f"(c[1]), "+f"(c[2]), "+f"(c[3])
        : "r"(a[0]), "r"(a[1]), "r"(a[2]), "r"(a[3]), "r"(b[0]), "r"(b[1]));
}
__device__ __forceinline__ void split_pack2(float x, float y, uint32_t& hi, uint32_t& lo) {
    __nv_bfloat16 hx = __float2bfloat16_rn(x);
    __nv_bfloat16 hy = __float2bfloat16_rn(y);
    __nv_bfloat162 hp = __halves2bfloat162(hx, hy);
    hi = *reinterpret_cast<uint32_t*>(&hp);
    __nv_bfloat162 lp = __floats2bfloat162_rn(x - __bfloat162float(hx),
                                              y - __bfloat162float(hy));
    lo = *reinterpret_cast<uint32_t*>(&lp);
}
__device__ __forceinline__ void cp16(uint32_t s, const void* g) {
    asm volatile("cp.async.cg.shared.global [%0], [%1], 16;" :: "r"(s), "l"(g));
}
__device__ __forceinline__ void cp_commit() { asm volatile("cp.async.commit_group;"); }
template <int N> __device__ __forceinline__ void cp_wait() {
    asm volatile("cp.async.wait_group %0;" :: "n"(N));
}

// ---------------------------------------------------------------------------
// split pre-pass: fp32 -> (hi bf16, lo bf16), 4 elements / thread
// ---------------------------------------------------------------------------
__global__ __launch_bounds__(256) void split_kernel(
    const float* __restrict__ src, __nv_bfloat16* __restrict__ h,
    __nv_bfloat16* __restrict__ l)
{
    size_t i = ((size_t)blockIdx.x * 256 + threadIdx.x) * 4;
    float4 v = *(const float4*)(src + i);
    uint32_t h0, l0, h1, l1;
    split_pack2(v.x, v.y, h0, l0);
    split_pack2(v.z, v.w, h1, l1);
    uint2 hv = { h0, h1 }, lv = { l0, l1 };
    *(uint2*)(h + i) = hv;
    *(uint2*)(l + i) = lv;
}

// ---------------------------------------------------------------------------
// Projection GEMM, pure bf16 split, cp.async double-buffered.
// Block 128(M) x 128(N), K-step 32, 8 warps (warp tile 64x32).
// z selects Q/K/V; output bf16 hi/lo, permuted [B,NH,S,HS]; Q scaled by 1/8.
// ---------------------------------------------------------------------------
struct ProjSmem {
    __nv_bfloat16 AsH[2][128][40];
    __nv_bfloat16 AsL[2][128][40];
    __nv_bfloat16 BsH[2][32][136];
    __nv_bfloat16 BsL[2][32][136];
};

__global__ __launch_bounds__(256, 2) void proj_kernel(
    const float* __restrict__ bq, const float* __restrict__ bk,
    const float* __restrict__ bv)
{
    extern __shared__ char smem_raw[];
    ProjSmem& sm = *reinterpret_cast<ProjSmem*>(smem_raw);

    const int z = blockIdx.z;
    const __nv_bfloat16* Ah = g_Xh + (z ? (size_t)8192 * 1024 : 0);
    const __nv_bfloat16* Al = g_Xl + (z ? (size_t)8192 * 1024 : 0);
    const __nv_bfloat16* Wh = g_Wh + (size_t)z * 1024 * 1024;
    const __nv_bfloat16* Wl = g_Wl + (size_t)z * 1024 * 1024;
    const float* bias = (z == 0) ? bq : (z == 1) ? bk : bv;
    __nv_bfloat16* outh = (z == 0) ? g_Qh : (z == 1) ? g_Kh : g_Vh;
    __nv_bfloat16* outl = (z == 0) ? g_Ql : (z == 1) ? g_Kl : g_Vl;
    const float scale = (z == 0) ? 0.125f : 1.0f;

    const int tid  = threadIdx.x;
    const int warp = tid >> 5;
    const int lane = tid & 31;
    const int g    = lane >> 2;
    const int tg   = lane & 3;

    const int m0 = blockIdx.y * 128;
    const int n0 = blockIdx.x * 128;
    const int wm = (warp >> 2) * 64;
    const int wn = (warp & 3) * 32;

    // cp.async mapping
    const int a_r = tid >> 1, a_c = (tid & 1) * 16;       // A: 128 rows x 32
    const int b_r = tid >> 3, b_c = (tid & 7) * 16;       // B: 32 rows x 128

    auto issue = [&](int st, int k0) {
        const __nv_bfloat16* gah = Ah + (size_t)(m0 + a_r) * 1024 + k0 + a_c;
        const __nv_bfloat16* gal = Al + (size_t)(m0 + a_r) * 1024 + k0 + a_c;
        cp16(smem_u32(&sm.AsH[st][a_r][a_c]),     gah);
        cp16(smem_u32(&sm.AsH[st][a_r][a_c + 8]), gah + 8);
        cp16(smem_u32(&sm.AsL[st][a_r][a_c]),     gal);
        cp16(smem_u32(&sm.AsL[st][a_r][a_c + 8]), gal + 8);
        const __nv_bfloat16* gbh = Wh + (size_t)(k0 + b_r) * 1024 + n0 + b_c;
        const __nv_bfloat16* gbl = Wl + (size_t)(k0 + b_r) * 1024 + n0 + b_c;
        cp16(smem_u32(&sm.BsH[st][b_r][b_c]),     gbh);
        cp16(smem_u32(&sm.BsH[st][b_r][b_c + 8]), gbh + 8);
        cp16(smem_u32(&sm.BsL[st][b_r][b_c]),     gbl);
        cp16(smem_u32(&sm.BsL[st][b_r][b_c + 8]), gbl + 8);
    };

    float acc[4][4][4] = {};

    issue(0, 0);
    cp_commit();

    const int ar = wm + (lane & 15);
    const int acol = (lane >> 4) * 8;
    const int l7 = lane & 7;
    const int khalf = (lane >> 3) & 1;
    const int nhalf = lane >> 4;

    for (int it = 0; it < 32; it++) {
        if (it + 1 < 32) { issue((it + 1) & 1, (it + 1) * 32); cp_commit(); cp_wait<1>(); }
        else             { cp_wait<0>(); }
        __syncthreads();
        const int st = it & 1;

#pragma unroll
        for (int kk = 0; kk < 32; kk += 16) {
            // B fragments: 4 n8 tiles via 2 x4t loads (hi + lo)
            uint32_t bH[4][2], bL[4][2];
#pragma unroll
            for (int p = 0; p < 2; p++) {
                uint32_t r4[4];
                ldsm_x4t(r4, smem_u32(&sm.BsH[st][kk + khalf * 8 + l7][wn + p * 16 + nhalf * 8]));
                bH[2 * p][0] = r4[0]; bH[2 * p][1] = r4[1];
                bH[2 * p + 1][0] = r4[2]; bH[2 * p + 1][1] = r4[3];
                ldsm_x4t(r4, smem_u32(&sm.BsL[st][kk + khalf * 8 + l7][wn + p * 16 + nhalf * 8]));
                bL[2 * p][0] = r4[0]; bL[2 * p][1] = r4[1];
                bL[2 * p + 1][0] = r4[2]; bL[2 * p + 1][1] = r4[3];
            }
#pragma unroll
            for (int mi = 0; mi < 4; mi++) {
                uint32_t aH[4], aL[4];
                ldsm_x4(aH, smem_u32(&sm.AsH[st][ar + mi * 16][kk + acol]));
                ldsm_x4(aL, smem_u32(&sm.AsL[st][ar + mi * 16][kk + acol]));
#pragma unroll
                for (int ni = 0; ni < 4; ni++) {
                    mma16816(acc[mi][ni], aH, bH[ni]);
                    mma16816(acc[mi][ni], aH, bL[ni]);
                    mma16816(acc[mi][ni], aL, bH[ni]);
                }
            }
        }
        __syncthreads();
    }

    // epilogue: bias, scale, split, permuted bf16 store
#pragma unroll
    for (int ni = 0; ni < 4; ni++) {
        const int col = n0 + wn + ni * 8 + tg * 2;
        const int head = col >> 6;
        const int d = col & 63;
        float2 b2 = *(const float2*)&bias[col];
#pragma unroll
        for (int mi = 0; mi < 4; mi++) {
#pragma unroll
            for (int half = 0; half < 2; half++) {
                int m  = m0 + wm + mi * 16 + g + half * 8;
                int bi = m >> 11, si = m & 2047;
                float x = (acc[mi][ni][2 * half]     + b2.x) * scale;
                float y = (acc[mi][ni][2 * half + 1] + b2.y) * scale;
                uint32_t hi, lo;
                split_pack2(x, y, hi, lo);
                size_t idx = (((size_t)bi * NH + head) * 2048 + si) * HS + d;
                *(uint32_t*)&outh[idx] = hi;
                *(uint32_t*)&outl[idx] = lo;
            }
        }
    }
}

// ---------------------------------------------------------------------------
// Flash attention: bf16 split, cp.async double-buffered K/V, online softmax.
// Block 128 F-rows x 64 T-tile, 8 warps (one m16 band each).
// ---------------------------------------------------------------------------
struct AttnSmem {
    __nv_bfloat16 KH[2][64][72];
    __nv_bfloat16 KL[2][64][72];
    __nv_bfloat16 VH[2][64][72];
    __nv_bfloat16 VL[2][64][72];
};

__global__ __launch_bounds__(256, 2) void attn_kernel(
    const float* __restrict__ mask,   // [B, F, T]
    float* __restrict__ out)          // [B, F, NH, HS]
{
    extern __shared__ char smem_raw[];
    AttnSmem& sm = *reinterpret_cast<AttnSmem*>(smem_raw);

    const int tid  = threadIdx.x;
    const int warp = tid >> 5;
    const int lane = tid & 31;
    const int g    = lane >> 2;
    const int tg   = lane & 3;

    const int f0 = blockIdx.x * 128;
    const int n  = blockIdx.y;
    const int b  = blockIdx.z;
    const size_t hb = (size_t)b * NH + n;

    const __nv_bfloat16* Qh = g_Qh + (hb * Fdim + f0 + warp * 16) * HS;
    const __nv_bfloat16* Ql = g_Ql + (hb * Fdim + f0 + warp * 16) * HS;
    const __nv_bfloat16* Kh = g_Kh + hb * Tdim * HS;
    const __nv_bfloat16* Kl = g_Kl + hb * Tdim * HS;
    const __nv_bfloat16* Vh = g_Vh + hb * Tdim * HS;
    const __nv_bfloat16* Vl = g_Vl + hb * Tdim * HS;
    const float* Mw = mask + ((size_t)b * Fdim + f0 + warp * 16) * Tdim;

    // Q fragments direct from gmem (already scaled by 1/8)
    uint32_t qH[4][4], qL[4][4];
#pragma unroll
    for (int kc = 0; kc < 4; kc++) {
        qH[kc][0] = *(const uint32_t*)(Qh + (size_t)g * HS + kc * 16 + tg * 2);
        qH[kc][1] = *(const uint32_t*)(Qh + (size_t)(g + 8) * HS + kc * 16 + tg * 2);
        qH[kc][2] = *(const uint32_t*)(Qh + (size_t)g * HS + kc * 16 + 8 + tg * 2);
        qH[kc][3] = *(const uint32_t*)(Qh + (size_t)(g + 8) * HS + kc * 16 + 8 + tg * 2);
        qL[kc][0] = *(const uint32_t*)(Ql + (size_t)g * HS + kc * 16 + tg * 2);
        qL[kc][1] = *(const uint32_t*)(Ql + (size_t)(g + 8) * HS + kc * 16 + tg * 2);
        qL[kc][2] = *(const uint32_t*)(Ql + (size_t)g * HS + kc * 16 + 8 + tg * 2);
        qL[kc][3] = *(const uint32_t*)(Ql + (size_t)(g + 8) * HS + kc * 16 + 8 + tg * 2);
    }

    // cp.async mapping: 64 rows x 64 cols per array
    const int ld_r = tid >> 2;
    const int ld_c = (tid & 3) * 16;

    auto issue = [&](int st, int t0) {
        const size_t go = (size_t)(t0 + ld_r) * HS + ld_c;
        cp16(smem_u32(&sm.KH[st][ld_r][ld_c]),     Kh + go);
        cp16(smem_u32(&sm.KH[st][ld_r][ld_c + 8]), Kh + go + 8);
        cp16(smem_u32(&sm.KL[st][ld_r][ld_c]),     Kl + go);
        cp16(smem_u32(&sm.KL[st][ld_r][ld_c + 8]), Kl + go + 8);
        cp16(smem_u32(&sm.VH[st][ld_r][ld_c]),     Vh + go);
        cp16(smem_u32(&sm.VH[st][ld_r][ld_c + 8]), Vh + go + 8);
        cp16(smem_u32(&sm.VL[st][ld_r][ld_c]),     Vl + go);
        cp16(smem_u32(&sm.VL[st][ld_r][ld_c + 8]), Vl + go + 8);
    };

    float o[8][4] = {};
    float mrow0 = -1e30f, mrow1 = -1e30f, l0 = 0.f, l1 = 0.f;

    issue(0, 0);
    cp_commit();

    const int l7 = lane & 7;
    const int half8 = (lane >> 3) & 1;
    const int quad  = lane >> 4;

    for (int it = 0; it < 32; it++) {
        const int t0 = it * 64;
        if (it + 1 < 32) { issue((it + 1) & 1, t0 + 64); cp_commit(); cp_wait<1>(); }
        else             { cp_wait<0>(); }
        __syncthreads();
        const int st = it & 1;

        // S = Q K^T
        float s[8][4];
#pragma unroll
        for (int ni = 0; ni < 8; ni++)
            s[ni][0] = s[ni][1] = s[ni][2] = s[ni][3] = 0.f;

#pragma unroll
        for (int np = 0; np < 4; np++) {
            const int krow = np * 16 + quad * 8 + l7;
#pragma unroll
            for (int kc = 0; kc < 4; kc++) {
                uint32_t k4h[4], k4l[4];
                ldsm_x4(k4h, smem_u32(&sm.KH[st][krow][kc * 16 + half8 * 8]));
                ldsm_x4(k4l, smem_u32(&sm.KL[st][krow][kc * 16 + half8 * 8]));
                mma16816(s[2 * np],     qH[kc], k4h);
                mma16816(s[2 * np],     qH[kc], k4l);
                mma16816(s[2 * np],     qL[kc], k4h);
                mma16816(s[2 * np + 1], qH[kc], k4h + 2);
                mma16816(s[2 * np + 1], qH[kc], k4l + 2);
                mma16816(s[2 * np + 1], qL[kc], k4h + 2);
            }
        }

        // mask adder
#pragma unroll
        for (int ni = 0; ni < 8; ni++) {
            float2 mm0 = *(const float2*)&Mw[(size_t)g * Tdim + t0 + ni * 8 + tg * 2];
            float2 mm1 = *(const float2*)&Mw[(size_t)(g + 8) * Tdim + t0 + ni * 8 + tg * 2];
            s[ni][0] += (1.f - mm0.x) * (-10000.f);
            s[ni][1] += (1.f - mm0.y) * (-10000.f);
            s[ni][2] += (1.f - mm1.x) * (-10000.f);
            s[ni][3] += (1.f - mm1.y) * (-10000.f);
        }

        // online softmax (rows g, g+8 spread over 4 lanes)
        float rmax0 = -1e30f, rmax1 = -1e30f;
#pragma unroll
        for (int ni = 0; ni < 8; ni++) {
            rmax0 = fmaxf(rmax0, fmaxf(s[ni][0], s[ni][1]));
            rmax1 = fmaxf(rmax1, fmaxf(s[ni][2], s[ni][3]));
        }
        rmax0 = fmaxf(rmax0, __shfl_xor_sync(0xffffffffu, rmax0, 1));
        rmax0 = fmaxf(rmax0, __shfl_xor_sync(0xffffffffu, rmax0, 2));
        rmax1 = fmaxf(rmax1, __shfl_xor_sync(0xffffffffu, rmax1, 1));
        rmax1 = fmaxf(rmax1, __shfl_xor_sync(0xffffffffu, rmax1, 2));

        float mnew0 = fmaxf(mrow0, rmax0);
        float mnew1 = fmaxf(mrow1, rmax1);
        float esc0 = __expf(mrow0 - mnew0);
        float esc1 = __expf(mrow1 - mnew1);
        mrow0 = mnew0;  mrow1 = mnew1;

        float rs0 = 0.f, rs1 = 0.f;
#pragma unroll
        for (int ni = 0; ni < 8; ni++) {
            s[ni][0] = __expf(s[ni][0] - mnew0);
            s[ni][1] = __expf(s[ni][1] - mnew0);
            s[ni][2] = __expf(s[ni][2] - mnew1);
            s[ni][3] = __expf(s[ni][3] - mnew1);
            rs0 += s[ni][0] + s[ni][1];
            rs1 += s[ni][2] + s[ni][3];
        }
        rs0 += __shfl_xor_sync(0xffffffffu, rs0, 1);
        rs0 += __shfl_xor_sync(0xffffffffu, rs0, 2);
        rs1 += __shfl_xor_sync(0xffffffffu, rs1, 1);
        rs1 += __shfl_xor_sync(0xffffffffu, rs1, 2);

        l0 = l0 * esc0 + rs0;
        l1 = l1 * esc1 + rs1;
#pragma unroll
        for (int di = 0; di < 8; di++) {
            o[di][0] *= esc0;  o[di][1] *= esc0;
            o[di][2] *= esc1;  o[di][3] *= esc1;
        }

        // O += P V
#pragma unroll
        for (int kc = 0; kc < 4; kc++) {
            uint32_t pH[4], pL[4];
            split_pack2(s[2 * kc][0],     s[2 * kc][1],     pH[0], pL[0]);
            split_pack2(s[2 * kc][2],     s[2 * kc][3],     pH[1], pL[1]);
            split_pack2(s[2 * kc + 1][0], s[2 * kc + 1][1], pH[2], pL[2]);
            split_pack2(s[2 * kc + 1][2], s[2 * kc + 1][3], pH[3], pL[3]);
            const int vrow = kc * 16 + half8 * 8 + l7;
#pragma unroll
            for (int dp = 0; dp < 4; dp++) {
                uint32_t v4h[4], v4l[4];
                ldsm_x4t(v4h, smem_u32(&sm.VH[st][vrow][dp * 16 + quad * 8]));
                ldsm_x4t(v4l, smem_u32(&sm.VL[st][vrow][dp * 16 + quad * 8]));
                mma16816(o[2 * dp],     pH, v4h);
                mma16816(o[2 * dp],     pH, v4l);
                mma16816(o[2 * dp],     pL, v4h);
                mma16816(o[2 * dp + 1], pH, v4h + 2);
                mma16816(o[2 * dp + 1], pH, v4l + 2);
                mma16816(o[2 * dp + 1], pL, v4h + 2);
            }
        }
        __syncthreads();
    }

    // epilogue
    const float inv0 = 1.f / l0;
    const float inv1 = 1.f / l1;
    const int f = f0 + warp * 16 + g;
    float* orow0 = out + (((size_t)b * Fdim + f) * NH + n) * HS;
    float* orow1 = out + (((size_t)b * Fdim + f + 8) * NH + n) * HS;
#pragma unroll
    for (int di = 0; di < 8; di++) {
        float2 r0 = { o[di][0] * inv0, o[di][1] * inv0 };
        float2 r1 = { o[di][2] * inv1, o[di][3] * inv1 };
        *(float2*)&orow0[di * 8 + tg * 2] = r0;
        *(float2*)&orow1[di * 8 + tg * 2] = r1;
    }
}

// ---------------------------------------------------------------------------
extern "C" void kernel_launch(void* const* d_in, const int* in_sizes, int n_in,
                              void* d_out, int out_size)
{
    const float* from = (const float*)d_in[0];
    const float* to   = (const float*)d_in[1];
    const float* mask = (const float*)d_in[2];
    const float* Wq   = (const float*)d_in[3];
    const float* bq   = (const float*)d_in[4];
    const float* Wk   = (const float*)d_in[5];
    const float* bk   = (const float*)d_in[6];
    const float* Wv   = (const float*)d_in[7];
    const float* bv   = (const float*)d_in[8];
    float* out = (float*)d_out;

    cudaFuncSetAttribute(proj_kernel, cudaFuncAttributeMaxDynamicSharedMemorySize,
                         (int)sizeof(ProjSmem));
    cudaFuncSetAttribute(attn_kernel, cudaFuncAttributeMaxDynamicSharedMemorySize,
                         (int)sizeof(AttnSmem));

    __nv_bfloat16 *xh, *xl, *wh, *wl;
    cudaGetSymbolAddress((void**)&xh, g_Xh);
    cudaGetSymbolAddress((void**)&xl, g_Xl);
    cudaGetSymbolAddress((void**)&wh, g_Wh);
    cudaGetSymbolAddress((void**)&wl, g_Wl);

    // split pre-pass: X(from), X(to), Wq, Wk, Wv
    split_kernel<<<8192, 256>>>(from, xh, xl);
    split_kernel<<<8192, 256>>>(to,   xh + (size_t)8192 * 1024, xl + (size_t)8192 * 1024);
    split_kernel<<<1024, 256>>>(Wq, wh,                         wl);
    split_kernel<<<1024, 256>>>(Wk, wh + (size_t)1024 * 1024,   wl + (size_t)1024 * 1024);
    split_kernel<<<1024, 256>>>(Wv, wh + (size_t)2048 * 1024,   wl + (size_t)2048 * 1024);

    dim3 pgrid(Hdim / 128, (Bsz * Fdim) / 128, 3);
    proj_kernel<<<pgrid, 256, sizeof(ProjSmem)>>>(bq, bk, bv);

    dim3 agrid(Fdim / 128, NH, Bsz);
    attn_kernel<<<agrid, 256, sizeof(AttnSmem)>>>(mask, out);
}

// round 6
// speedup vs baseline: 2.4800x; 1.0001x over previous
#include <cuda_runtime.h>
#include <cuda_bf16.h>
#include <math.h>
#include <stdint.h>

constexpr int Bsz  = 4;
constexpr int Fdim = 2048;
constexpr int Tdim = 2048;
constexpr int Hdim = 1024;
constexpr int NH   = 16;
constexpr int HS   = 64;

// ---------------------------------------------------------------------------
// bf16 split scratch (hi + lo), all in gmem
// ---------------------------------------------------------------------------
// X: rows 0..8191 = from_tensor, rows 8192..16383 = to_tensor   [16384 x 1024]
__device__ __nv_bfloat16 g_Xh[(size_t)16384 * 1024];
__device__ __nv_bfloat16 g_Xl[(size_t)16384 * 1024];
// W: z-th slice is Wq / Wk / Wv   [3 x 1024 x 1024]
__device__ __nv_bfloat16 g_Wh[(size_t)3 * 1024 * 1024];
__device__ __nv_bfloat16 g_Wl[(size_t)3 * 1024 * 1024];
// projected Q/K/V  [B, NH, S, HS]  (Q pre-scaled by 1/8)
__device__ __nv_bfloat16 g_Qh[(size_t)Bsz * NH * Fdim * HS];
__device__ __nv_bfloat16 g_Ql[(size_t)Bsz * NH * Fdim * HS];
__device__ __nv_bfloat16 g_Kh[(size_t)Bsz * NH * Tdim * HS];
__device__ __nv_bfloat16 g_Kl[(size_t)Bsz * NH * Tdim * HS];
__device__ __nv_bfloat16 g_Vh[(size_t)Bsz * NH * Tdim * HS];
__device__ __nv_bfloat16 g_Vl[(size_t)Bsz * NH * Tdim * HS];

// ---------------------------------------------------------------------------
// helpers
// ---------------------------------------------------------------------------
__device__ __forceinline__ uint32_t smem_u32(const void* p) {
    return (uint32_t)__cvta_generic_to_shared(p);
}
__device__ __forceinline__ void ldsm_x4(uint32_t* r, uint32_t a) {
    asm volatile("ldmatrix.sync.aligned.m8n8.x4.shared.b16 {%0,%1,%2,%3}, [%4];"
                 : "=r"(r[0]), "=r"(r[1]), "=r"(r[2]), "=r"(r[3]) : "r"(a));
}
__device__ __forceinline__ void ldsm_x4t(uint32_t* r, uint32_t a) {
    asm volatile("ldmatrix.sync.aligned.m8n8.x4.trans.shared.b16 {%0,%1,%2,%3}, [%4];"
                 : "=r"(r[0]), "=r"(r[1]), "=r"(r[2]), "=r"(r[3]) : "r"(a));
}
__device__ __forceinline__ void mma16816(float* c, const uint32_t* a, const uint32_t* b) {
    asm volatile(
        "mma.sync.aligned.m16n8k16.row.col.f32.bf16.bf16.f32 "
        "{%0,%1,%2,%3}, {%4,%5,%6,%7}, {%8,%9}, {%0,%1,%2,%3};"
        : "+f"(c[0]), "+f"(c[1]), "+f"(c[2]), "+f"(c[3])
        : "r"(a[0]), "r"(a[1]), "r"(a[2]), "r"(a[3]), "r"(b[0]), "r"(b[1]));
}
__device__ __forceinline__ void split_pack2(float x, float y, uint32_t& hi, uint32_t& lo) {
    __nv_bfloat16 hx = __float2bfloat16_rn(x);
    __nv_bfloat16 hy = __float2bfloat16_rn(y);
    __nv_bfloat162 hp = __halves2bfloat162(hx, hy);
    hi = *reinterpret_cast<uint32_t*>(&hp);
    __nv_bfloat162 lp = __floats2bfloat162_rn(x - __bfloat162float(hx),
                                              y - __bfloat162float(hy));
    lo = *reinterpret_cast<uint32_t*>(&lp);
}
__device__ __forceinline__ void cp16(uint32_t s, const void* g) {
    asm volatile("cp.async.cg.shared.global [%0], [%1], 16;" :: "r"(s), "l"(g));
}
__device__ __forceinline__ void cp_commit() { asm volatile("cp.async.commit_group;"); }
template <int N> __device__ __forceinline__ void cp_wait() {
    asm volatile("cp.async.wait_group %0;" :: "n"(N));
}

// ---------------------------------------------------------------------------
// split pre-pass: fp32 -> (hi bf16, lo bf16), 4 elements / thread
// ---------------------------------------------------------------------------
__global__ __launch_bounds__(256) void split_kernel(
    const float* __restrict__ src, __nv_bfloat16* __restrict__ h,
    __nv_bfloat16* __restrict__ l)
{
    size_t i = ((size_t)blockIdx.x * 256 + threadIdx.x) * 4;
    float4 v = *(const float4*)(src + i);
    uint32_t h0, l0, h1, l1;
    split_pack2(v.x, v.y, h0, l0);
    split_pack2(v.z, v.w, h1, l1);
    uint2 hv = { h0, h1 }, lv = { l0, l1 };
    *(uint2*)(h + i) = hv;
    *(uint2*)(l + i) = lv;
}

// ---------------------------------------------------------------------------
// Projection GEMM, pure bf16 split, cp.async double-buffered.
// Block 128(M) x 128(N), K-step 32, 8 warps (warp tile 64x32).
// z selects Q/K/V; output bf16 hi/lo, permuted [B,NH,S,HS]; Q scaled by 1/8.
// ---------------------------------------------------------------------------
struct ProjSmem {
    __nv_bfloat16 AsH[2][128][40];
    __nv_bfloat16 AsL[2][128][40];
    __nv_bfloat16 BsH[2][32][136];
    __nv_bfloat16 BsL[2][32][136];
};

__global__ __launch_bounds__(256, 2) void proj_kernel(
    const float* __restrict__ bq, const float* __restrict__ bk,
    const float* __restrict__ bv)
{
    extern __shared__ char smem_raw[];
    ProjSmem& sm = *reinterpret_cast<ProjSmem*>(smem_raw);

    const int z = blockIdx.z;
    const __nv_bfloat16* Ah = g_Xh + (z ? (size_t)8192 * 1024 : 0);
    const __nv_bfloat16* Al = g_Xl + (z ? (size_t)8192 * 1024 : 0);
    const __nv_bfloat16* Wh = g_Wh + (size_t)z * 1024 * 1024;
    const __nv_bfloat16* Wl = g_Wl + (size_t)z * 1024 * 1024;
    const float* bias = (z == 0) ? bq : (z == 1) ? bk : bv;
    __nv_bfloat16* outh = (z == 0) ? g_Qh : (z == 1) ? g_Kh : g_Vh;
    __nv_bfloat16* outl = (z == 0) ? g_Ql : (z == 1) ? g_Kl : g_Vl;
    const float scale = (z == 0) ? 0.125f : 1.0f;

    const int tid  = threadIdx.x;
    const int warp = tid >> 5;
    const int lane = tid & 31;
    const int g    = lane >> 2;
    const int tg   = lane & 3;

    const int m0 = blockIdx.y * 128;
    const int n0 = blockIdx.x * 128;
    const int wm = (warp >> 2) * 64;
    const int wn = (warp & 3) * 32;

    // cp.async mapping
    const int a_r = tid >> 1, a_c = (tid & 1) * 16;       // A: 128 rows x 32
    const int b_r = tid >> 3, b_c = (tid & 7) * 16;       // B: 32 rows x 128

    auto issue = [&](int st, int k0) {
        const __nv_bfloat16* gah = Ah + (size_t)(m0 + a_r) * 1024 + k0 + a_c;
        const __nv_bfloat16* gal = Al + (size_t)(m0 + a_r) * 1024 + k0 + a_c;
        cp16(smem_u32(&sm.AsH[st][a_r][a_c]),     gah);
        cp16(smem_u32(&sm.AsH[st][a_r][a_c + 8]), gah + 8);
        cp16(smem_u32(&sm.AsL[st][a_r][a_c]),     gal);
        cp16(smem_u32(&sm.AsL[st][a_r][a_c + 8]), gal + 8);
        const __nv_bfloat16* gbh = Wh + (size_t)(k0 + b_r) * 1024 + n0 + b_c;
        const __nv_bfloat16* gbl = Wl + (size_t)(k0 + b_r) * 1024 + n0 + b_c;
        cp16(smem_u32(&sm.BsH[st][b_r][b_c]),     gbh);
        cp16(smem_u32(&sm.BsH[st][b_r][b_c + 8]), gbh + 8);
        cp16(smem_u32(&sm.BsL[st][b_r][b_c]),     gbl);
        cp16(smem_u32(&sm.BsL[st][b_r][b_c + 8]), gbl + 8);
    };

    float acc[4][4][4] = {};

    issue(0, 0);
    cp_commit();

    const int ar = wm + (lane & 15);
    const int acol = (lane >> 4) * 8;
    const int l7 = lane & 7;
    const int khalf = (lane >> 3) & 1;
    const int nhalf = lane >> 4;

    for (int it = 0; it < 32; it++) {
        if (it + 1 < 32) { issue((it + 1) & 1, (it + 1) * 32); cp_commit(); cp_wait<1>(); }
        else             { cp_wait<0>(); }
        __syncthreads();
        const int st = it & 1;

#pragma unroll
        for (int kk = 0; kk < 32; kk += 16) {
            // B fragments: 4 n8 tiles via 2 x4t loads (hi + lo)
            uint32_t bH[4][2], bL[4][2];
#pragma unroll
            for (int p = 0; p < 2; p++) {
                uint32_t r4[4];
                ldsm_x4t(r4, smem_u32(&sm.BsH[st][kk + khalf * 8 + l7][wn + p * 16 + nhalf * 8]));
                bH[2 * p][0] = r4[0]; bH[2 * p][1] = r4[1];
                bH[2 * p + 1][0] = r4[2]; bH[2 * p + 1][1] = r4[3];
                ldsm_x4t(r4, smem_u32(&sm.BsL[st][kk + khalf * 8 + l7][wn + p * 16 + nhalf * 8]));
                bL[2 * p][0] = r4[0]; bL[2 * p][1] = r4[1];
                bL[2 * p + 1][0] = r4[2]; bL[2 * p + 1][1] = r4[3];
            }
#pragma unroll
            for (int mi = 0; mi < 4; mi++) {
                uint32_t aH[4], aL[4];
                ldsm_x4(aH, smem_u32(&sm.AsH[st][ar + mi * 16][kk + acol]));
                ldsm_x4(aL, smem_u32(&sm.AsL[st][ar + mi * 16][kk + acol]));
#pragma unroll
                for (int ni = 0; ni < 4; ni++) {
                    mma16816(acc[mi][ni], aH, bH[ni]);
                    mma16816(acc[mi][ni], aH, bL[ni]);
                    mma16816(acc[mi][ni], aL, bH[ni]);
                }
            }
        }
        __syncthreads();
    }

    // epilogue: bias, scale, split, permuted bf16 store
#pragma unroll
    for (int ni = 0; ni < 4; ni++) {
        const int col = n0 + wn + ni * 8 + tg * 2;
        const int head = col >> 6;
        const int d = col & 63;
        float2 b2 = *(const float2*)&bias[col];
#pragma unroll
        for (int mi = 0; mi < 4; mi++) {
#pragma unroll
            for (int half = 0; half < 2; half++) {
                int m  = m0 + wm + mi * 16 + g + half * 8;
                int bi = m >> 11, si = m & 2047;
                float x = (acc[mi][ni][2 * half]     + b2.x) * scale;
                float y = (acc[mi][ni][2 * half + 1] + b2.y) * scale;
                uint32_t hi, lo;
                split_pack2(x, y, hi, lo);
                size_t idx = (((size_t)bi * NH + head) * 2048 + si) * HS + d;
                *(uint32_t*)&outh[idx] = hi;
                *(uint32_t*)&outl[idx] = lo;
            }
        }
    }
}

// ---------------------------------------------------------------------------
// Flash attention: bf16 split, cp.async double-buffered K/V, online softmax.
// Block 128 F-rows x 64 T-tile, 8 warps (one m16 band each).
// ---------------------------------------------------------------------------
struct AttnSmem {
    __nv_bfloat16 KH[2][64][72];
    __nv_bfloat16 KL[2][64][72];
    __nv_bfloat16 VH[2][64][72];
    __nv_bfloat16 VL[2][64][72];
};

__global__ __launch_bounds__(256, 2) void attn_kernel(
    const float* __restrict__ mask,   // [B, F, T]
    float* __restrict__ out)          // [B, F, NH, HS]
{
    extern __shared__ char smem_raw[];
    AttnSmem& sm = *reinterpret_cast<AttnSmem*>(smem_raw);

    const int tid  = threadIdx.x;
    const int warp = tid >> 5;
    const int lane = tid & 31;
    const int g    = lane >> 2;
    const int tg   = lane & 3;

    const int f0 = blockIdx.x * 128;
    const int n  = blockIdx.y;
    const int b  = blockIdx.z;
    const size_t hb = (size_t)b * NH + n;

    const __nv_bfloat16* Qh = g_Qh + (hb * Fdim + f0 + warp * 16) * HS;
    const __nv_bfloat16* Ql = g_Ql + (hb * Fdim + f0 + warp * 16) * HS;
    const __nv_bfloat16* Kh = g_Kh + hb * Tdim * HS;
    const __nv_bfloat16* Kl = g_Kl + hb * Tdim * HS;
    const __nv_bfloat16* Vh = g_Vh + hb * Tdim * HS;
    const __nv_bfloat16* Vl = g_Vl + hb * Tdim * HS;
    const float* Mw = mask + ((size_t)b * Fdim + f0 + warp * 16) * Tdim;

    // Q fragments direct from gmem (already scaled by 1/8)
    uint32_t qH[4][4], qL[4][4];
#pragma unroll
    for (int kc = 0; kc < 4; kc++) {
        qH[kc][0] = *(const uint32_t*)(Qh + (size_t)g * HS + kc * 16 + tg * 2);
        qH[kc][1] = *(const uint32_t*)(Qh + (size_t)(g + 8) * HS + kc * 16 + tg * 2);
        qH[kc][2] = *(const uint32_t*)(Qh + (size_t)g * HS + kc * 16 + 8 + tg * 2);
        qH[kc][3] = *(const uint32_t*)(Qh + (size_t)(g + 8) * HS + kc * 16 + 8 + tg * 2);
        qL[kc][0] = *(const uint32_t*)(Ql + (size_t)g * HS + kc * 16 + tg * 2);
        qL[kc][1] = *(const uint32_t*)(Ql + (size_t)(g + 8) * HS + kc * 16 + tg * 2);
        qL[kc][2] = *(const uint32_t*)(Ql + (size_t)g * HS + kc * 16 + 8 + tg * 2);
        qL[kc][3] = *(const uint32_t*)(Ql + (size_t)(g + 8) * HS + kc * 16 + 8 + tg * 2);
    }

    // cp.async mapping: 64 rows x 64 cols per array
    const int ld_r = tid >> 2;
    const int ld_c = (tid & 3) * 16;

    auto issue = [&](int st, int t0) {
        const size_t go = (size_t)(t0 + ld_r) * HS + ld_c;
        cp16(smem_u32(&sm.KH[st][ld_r][ld_c]),     Kh + go);
        cp16(smem_u32(&sm.KH[st][ld_r][ld_c + 8]), Kh + go + 8);
        cp16(smem_u32(&sm.KL[st][ld_r][ld_c]),     Kl + go);
        cp16(smem_u32(&sm.KL[st][ld_r][ld_c + 8]), Kl + go + 8);
        cp16(smem_u32(&sm.VH[st][ld_r][ld_c]),     Vh + go);
        cp16(smem_u32(&sm.VH[st][ld_r][ld_c + 8]), Vh + go + 8);
        cp16(smem_u32(&sm.VL[st][ld_r][ld_c]),     Vl + go);
        cp16(smem_u32(&sm.VL[st][ld_r][ld_c + 8]), Vl + go + 8);
    };

    float o[8][4] = {};
    float mrow0 = -1e30f, mrow1 = -1e30f, l0 = 0.f, l1 = 0.f;

    issue(0, 0);
    cp_commit();

    const int l7 = lane & 7;
    const int half8 = (lane >> 3) & 1;
    const int quad  = lane >> 4;

    for (int it = 0; it < 32; it++) {
        const int t0 = it * 64;
        if (it + 1 < 32) { issue((it + 1) & 1, t0 + 64); cp_commit(); cp_wait<1>(); }
        else             { cp_wait<0>(); }
        __syncthreads();
        const int st = it & 1;

        // S = Q K^T
        float s[8][4];
#pragma unroll
        for (int ni = 0; ni < 8; ni++)
            s[ni][0] = s[ni][1] = s[ni][2] = s[ni][3] = 0.f;

#pragma unroll
        for (int np = 0; np < 4; np++) {
            const int krow = np * 16 + quad * 8 + l7;
#pragma unroll
            for (int kc = 0; kc < 4; kc++) {
                uint32_t k4h[4], k4l[4];
                ldsm_x4(k4h, smem_u32(&sm.KH[st][krow][kc * 16 + half8 * 8]));
                ldsm_x4(k4l, smem_u32(&sm.KL[st][krow][kc * 16 + half8 * 8]));
                mma16816(s[2 * np],     qH[kc], k4h);
                mma16816(s[2 * np],     qH[kc], k4l);
                mma16816(s[2 * np],     qL[kc], k4h);
                mma16816(s[2 * np + 1], qH[kc], k4h + 2);
                mma16816(s[2 * np + 1], qH[kc], k4l + 2);
                mma16816(s[2 * np + 1], qL[kc], k4h + 2);
            }
        }

        // mask adder
#pragma unroll
        for (int ni = 0; ni < 8; ni++) {
            float2 mm0 = *(const float2*)&Mw[(size_t)g * Tdim + t0 + ni * 8 + tg * 2];
            float2 mm1 = *(const float2*)&Mw[(size_t)(g + 8) * Tdim + t0 + ni * 8 + tg * 2];
            s[ni][0] += (1.f - mm0.x) * (-10000.f);
            s[ni][1] += (1.f - mm0.y) * (-10000.f);
            s[ni][2] += (1.f - mm1.x) * (-10000.f);
            s[ni][3] += (1.f - mm1.y) * (-10000.f);
        }

        // online softmax (rows g, g+8 spread over 4 lanes)
        float rmax0 = -1e30f, rmax1 = -1e30f;
#pragma unroll
        for (int ni = 0; ni < 8; ni++) {
            rmax0 = fmaxf(rmax0, fmaxf(s[ni][0], s[ni][1]));
            rmax1 = fmaxf(rmax1, fmaxf(s[ni][2], s[ni][3]));
        }
        rmax0 = fmaxf(rmax0, __shfl_xor_sync(0xffffffffu, rmax0, 1));
        rmax0 = fmaxf(rmax0, __shfl_xor_sync(0xffffffffu, rmax0, 2));
        rmax1 = fmaxf(rmax1, __shfl_xor_sync(0xffffffffu, rmax1, 1));
        rmax1 = fmaxf(rmax1, __shfl_xor_sync(0xffffffffu, rmax1, 2));

        float mnew0 = fmaxf(mrow0, rmax0);
        float mnew1 = fmaxf(mrow1, rmax1);
        float esc0 = __expf(mrow0 - mnew0);
        float esc1 = __expf(mrow1 - mnew1);
        mrow0 = mnew0;  mrow1 = mnew1;

        float rs0 = 0.f, rs1 = 0.f;
#pragma unroll
        for (int ni = 0; ni < 8; ni++) {
            s[ni][0] = __expf(s[ni][0] - mnew0);
            s[ni][1] = __expf(s[ni][1] - mnew0);
            s[ni][2] = __expf(s[ni][2] - mnew1);
            s[ni][3] = __expf(s[ni][3] - mnew1);
            rs0 += s[ni][0] + s[ni][1];
            rs1 += s[ni][2] + s[ni][3];
        }
        rs0 += __shfl_xor_sync(0xffffffffu, rs0, 1);
        rs0 += __shfl_xor_sync(0xffffffffu, rs0, 2);
        rs1 += __shfl_xor_sync(0xffffffffu, rs1, 1);
        rs1 += __shfl_xor_sync(0xffffffffu, rs1, 2);

        l0 = l0 * esc0 + rs0;
        l1 = l1 * esc1 + rs1;
#pragma unroll
        for (int di = 0; di < 8; di++) {
            o[di][0] *= esc0;  o[di][1] *= esc0;
            o[di][2] *= esc1;  o[di][3] *= esc1;
        }

        // O += P V
#pragma unroll
        for (int kc = 0; kc < 4; kc++) {
            uint32_t pH[4], pL[4];
            split_pack2(s[2 * kc][0],     s[2 * kc][1],     pH[0], pL[0]);
            split_pack2(s[2 * kc][2],     s[2 * kc][3],     pH[1], pL[1]);
            split_pack2(s[2 * kc + 1][0], s[2 * kc + 1][1], pH[2], pL[2]);
            split_pack2(s[2 * kc + 1][2], s[2 * kc + 1][3], pH[3], pL[3]);
            const int vrow = kc * 16 + half8 * 8 + l7;
#pragma unroll
            for (int dp = 0; dp < 4; dp++) {
                uint32_t v4h[4], v4l[4];
                ldsm_x4t(v4h, smem_u32(&sm.VH[st][vrow][dp * 16 + quad * 8]));
                ldsm_x4t(v4l, smem_u32(&sm.VL[st][vrow][dp * 16 + quad * 8]));
                mma16816(o[2 * dp],     pH, v4h);
                mma16816(o[2 * dp],     pH, v4l);
                mma16816(o[2 * dp],     pL, v4h);
                mma16816(o[2 * dp + 1], pH, v4h + 2);
                mma16816(o[2 * dp + 1], pH, v4l + 2);
                mma16816(o[2 * dp + 1], pL, v4h + 2);
            }
        }
        __syncthreads();
    }

    // epilogue
    const float inv0 = 1.f / l0;
    const float inv1 = 1.f / l1;
    const int f = f0 + warp * 16 + g;
    float* orow0 = out + (((size_t)b * Fdim + f) * NH + n) * HS;
    float* orow1 = out + (((size_t)b * Fdim + f + 8) * NH + n) * HS;
#pragma unroll
    for (int di = 0; di < 8; di++) {
        float2 r0 = { o[di][0] * inv0, o[di][1] * inv0 };
        float2 r1 = { o[di][2] * inv1, o[di][3] * inv1 };
        *(float2*)&orow0[di * 8 + tg * 2] = r0;
        *(float2*)&orow1[di * 8 + tg * 2] = r1;
    }
}

// ---------------------------------------------------------------------------
extern "C" void kernel_launch(void* const* d_in, const int* in_sizes, int n_in,
                              void* d_out, int out_size)
{
    const float* from = (const float*)d_in[0];
    const float* to   = (const float*)d_in[1];
    const float* mask = (const float*)d_in[2];
    const float* Wq   = (const float*)d_in[3];
    const float* bq   = (const float*)d_in[4];
    const float* Wk   = (const float*)d_in[5];
    const float* bk   = (const float*)d_in[6];
    const float* Wv   = (const float*)d_in[7];
    const float* bv   = (const float*)d_in[8];
    float* out = (float*)d_out;

    cudaFuncSetAttribute(proj_kernel, cudaFuncAttributeMaxDynamicSharedMemorySize,
                         (int)sizeof(ProjSmem));
    cudaFuncSetAttribute(attn_kernel, cudaFuncAttributeMaxDynamicSharedMemorySize,
                         (int)sizeof(AttnSmem));

    __nv_bfloat16 *xh, *xl, *wh, *wl;
    cudaGetSymbolAddress((void**)&xh, g_Xh);
    cudaGetSymbolAddress((void**)&xl, g_Xl);
    cudaGetSymbolAddress((void**)&wh, g_Wh);
    cudaGetSymbolAddress((void**)&wl, g_Wl);

    // split pre-pass: X(from), X(to), Wq, Wk, Wv
    split_kernel<<<8192, 256>>>(from, xh, xl);
    split_kernel<<<8192, 256>>>(to,   xh + (size_t)8192 * 1024, xl + (size_t)8192 * 1024);
    split_kernel<<<1024, 256>>>(Wq, wh,                         wl);
    split_kernel<<<1024, 256>>>(Wk, wh + (size_t)1024 * 1024,   wl + (size_t)1024 * 1024);
    split_kernel<<<1024, 256>>>(Wv, wh + (size_t)2048 * 1024,   wl + (size_t)2048 * 1024);

    dim3 pgrid(Hdim / 128, (Bsz * Fdim) / 128, 3);
    proj_kernel<<<pgrid, 256, sizeof(ProjSmem)>>>(bq, bk, bv);

    dim3 agrid(Fdim / 128, NH, Bsz);
    attn_kernel<<<agrid, 256, sizeof(AttnSmem)>>>(mask, out);
}